// round 7
// baseline (speedup 1.0000x reference)
#include <cuda_runtime.h>
#include <stdint.h>

// keep[b][n] = 1 if node n is in the top-k of batch b. B=16, N=2048.
__device__ unsigned char g_keep[16 * 2048];

// ---------------------------------------------------------------------------
// Kernel 1: exact top-k via 8-bit radix select (unchanged from R6, ~2-3us).
// Bin suffix-scan by ONE WARP with shfl. Keep set: u > T plus need_eq
// lowest-index elements with u == T. Bit-exact vs jax.lax.top_k.
// One block per batch, 512 threads. Ends with PDL trigger.
// ---------------------------------------------------------------------------
__global__ void __launch_bounds__(512)
topk_radix_kernel(const float* __restrict__ score, int N, int k) {
    __shared__ unsigned u[2048];
    __shared__ unsigned hist[256];
    __shared__ unsigned s_prefix, s_kk;

    const int b   = blockIdx.x;
    const int tid = threadIdx.x;
    const float* sc = score + (size_t)b * N;

    for (int t = tid; t < N; t += 512) {
        unsigned x = __float_as_uint(sc[t]);
        x ^= (x & 0x80000000u) ? 0xFFFFFFFFu : 0x80000000u;  // order-preserving
        u[t] = x;
    }
    if (tid == 0) { s_prefix = 0u; s_kk = (unsigned)k; }
    __syncthreads();

    for (int shift = 24; shift >= 0; shift -= 8) {
        const unsigned prefix = s_prefix;
        const unsigned kk     = s_kk;
        const unsigned pmask  = (shift == 24) ? 0u : (0xFFFFFFFFu << (shift + 8));

        if (tid < 256) hist[tid] = 0u;
        __syncthreads();

        for (int t = tid; t < N; t += 512) {
            unsigned x = u[t];
            if ((x & pmask) == prefix)
                atomicAdd(&hist[(x >> shift) & 0xFFu], 1u);
        }
        __syncthreads();

        if (tid < 32) {
            unsigned v[8], p[8];
            unsigned acc = 0u;
#pragma unroll
            for (int i = 0; i < 8; i++) {
                v[i] = hist[255 - (tid * 8 + i)];
                acc += v[i];
                p[i] = acc;
            }
            unsigned lane_excl = 0u, run = acc;
#pragma unroll
            for (int off = 1; off < 32; off <<= 1) {
                unsigned n0 = __shfl_up_sync(0xFFFFFFFFu, run, off);
                if ((int)(tid) >= off) { lane_excl += n0; run += n0; }
            }
#pragma unroll
            for (int i = 0; i < 8; i++) {
                unsigned incl = lane_excl + p[i];
                unsigned excl = incl - v[i];
                if (excl < kk && incl >= kk) {
                    int bin = 255 - (tid * 8 + i);
                    s_prefix = prefix | ((unsigned)bin << shift);
                    s_kk     = kk - excl;
                }
            }
        }
        __syncthreads();
    }

    const unsigned T        = s_prefix;
    const unsigned need_eq  = s_kk;
    const unsigned total_eq = hist[T & 0xFFu];

    for (int t = tid; t < N; t += 512) {
        unsigned x = u[t];
        unsigned char kp = 0u;
        if (x > T) {
            kp = 1u;
        } else if (x == T) {
            if (total_eq == need_eq) {
                kp = 1u;
            } else {
                unsigned c = 0u;
                for (int j = 0; j < t; j++) c += (u[j] == T);
                kp = (c < need_eq) ? 1u : 0u;
            }
        }
        g_keep[b * N + t] = kp;
    }

    __threadfence();
    __syncthreads();
    if (tid == 0) cudaTriggerProgrammaticLaunchCompletion();
}

// ---------------------------------------------------------------------------
// Kernel 2: out[b,i,j] = adj[b,i,j] * (keep[b,i] || keep[b,j])
// PDL secondary. TWO rows per block, 4 front-batched float4 loads per thread
// (MLP_p1=4) prefetched BEFORE cudaGridDependencySynchronize().
// Specialized for nvec == 2*blockDim (N=2048, 256 thr); generic fallback kept.
// ---------------------------------------------------------------------------
__global__ void __launch_bounds__(256)
apply_mask_kernel(const float4* __restrict__ adj,
                  float4* __restrict__ out, int N) {
    const int tid  = threadIdx.x;
    const int nvec = N >> 2;
    const int rowsPerBatch = N >> 1;            // pairs per batch

    int r  = blockIdx.x;                        // pair index
    int b  = r / rowsPerBatch;
    int i0 = (r - b * rowsPerBatch) * 2;
    int i1 = i0 + 1;

    size_t base0 = ((size_t)b * N + i0) * nvec;
    size_t base1 = base0 + nvec;

    if (nvec == 2 * (int)blockDim.x) {
        int j0 = tid, j1 = tid + blockDim.x;

        // 4 front-batched loads in flight across the dependency wait
        float4 v00 = adj[base0 + j0];
        float4 v01 = adj[base0 + j1];
        float4 v10 = adj[base1 + j0];
        float4 v11 = adj[base1 + j1];

        cudaGridDependencySynchronize();        // wait for g_keep

        const unsigned char* kb = g_keep + b * N;
        const uchar4*        km = (const uchar4*)kb;   // 2KB, L1-resident
        bool kept0 = (kb[i0] != 0);
        bool kept1 = (kb[i1] != 0);
        uchar4 m0 = km[j0];
        uchar4 m1 = km[j1];

        if (!kept0) {
            v00.x = m0.x ? v00.x : 0.0f;  v00.y = m0.y ? v00.y : 0.0f;
            v00.z = m0.z ? v00.z : 0.0f;  v00.w = m0.w ? v00.w : 0.0f;
            v01.x = m1.x ? v01.x : 0.0f;  v01.y = m1.y ? v01.y : 0.0f;
            v01.z = m1.z ? v01.z : 0.0f;  v01.w = m1.w ? v01.w : 0.0f;
        }
        if (!kept1) {
            v10.x = m0.x ? v10.x : 0.0f;  v10.y = m0.y ? v10.y : 0.0f;
            v10.z = m0.z ? v10.z : 0.0f;  v10.w = m0.w ? v10.w : 0.0f;
            v11.x = m1.x ? v11.x : 0.0f;  v11.y = m1.y ? v11.y : 0.0f;
            v11.z = m1.z ? v11.z : 0.0f;  v11.w = m1.w ? v11.w : 0.0f;
        }
        out[base0 + j0] = v00;
        out[base0 + j1] = v01;
        out[base1 + j0] = v10;
        out[base1 + j1] = v11;
    } else {
        // generic fallback for other shapes
        cudaGridDependencySynchronize();
        const unsigned char* kb = g_keep + b * N;
        const uchar4*        km = (const uchar4*)kb;
        bool kept0 = (kb[i0] != 0);
        bool kept1 = (kb[i1] != 0);
        for (int j = tid; j < nvec; j += blockDim.x) {
            uchar4 m = km[j];
            float4 v0 = adj[base0 + j];
            float4 v1 = adj[base1 + j];
            if (!kept0) {
                v0.x = m.x ? v0.x : 0.0f;  v0.y = m.y ? v0.y : 0.0f;
                v0.z = m.z ? v0.z : 0.0f;  v0.w = m.w ? v0.w : 0.0f;
            }
            if (!kept1) {
                v1.x = m.x ? v1.x : 0.0f;  v1.y = m.y ? v1.y : 0.0f;
                v1.z = m.z ? v1.z : 0.0f;  v1.w = m.w ? v1.w : 0.0f;
            }
            out[base0 + j] = v0;
            out[base1 + j] = v1;
        }
    }
}

extern "C" void kernel_launch(void* const* d_in, const int* in_sizes, int n_in,
                              void* d_out, int out_size) {
    const float* adj   = (const float*)d_in[0];   // [B, N, N] fp32
    const float* score = (const float*)d_in[1];   // [B, N, 1] fp32

    long long n_adj   = in_sizes[0];
    long long n_score = in_sizes[1];
    int N = (int)(n_adj / n_score);               // 2048
    int B = (int)(n_score / N);                   // 16
    int k = N / 2;                                // RATE = 0.5

    topk_radix_kernel<<<B, 512>>>(score, N, k);

    // PDL secondary: one block per row PAIR.
    cudaLaunchConfig_t cfg = {};
    cfg.gridDim  = dim3((unsigned)(B * N / 2));
    cfg.blockDim = dim3(256);
    cfg.stream   = 0;
    cudaLaunchAttribute attr[1];
    attr[0].id = cudaLaunchAttributeProgrammaticStreamSerialization;
    attr[0].val.programmaticStreamSerializationAllowed = 1;
    cfg.attrs    = attr;
    cfg.numAttrs = 1;
    cudaLaunchKernelEx(&cfg, apply_mask_kernel,
                       (const float4*)adj, (float4*)d_out, N);
}